// round 16
// baseline (speedup 1.0000x reference)
#include <cuda_runtime.h>
#include <cuda_fp16.h>
#include <math.h>
#include <stdint.h>

#define BMAX 65536

// ---- scratch (allocation-free rule: __device__ globals) ----
// bufA/bufB hold node-major activations: plane n at n*B64, element (n,b,c) at n*B64+b*64+c.
__device__ __align__(16) __half g_bufA[(size_t)BMAX * 17 * 64];
__device__ __align__(16) __half g_bufB[(size_t)BMAX * 17 * 64];
__device__ __align__(16) __half g_z[(size_t)BMAX * 256];
__device__ __align__(16) float g_xt[(size_t)17 * BMAX * 2];  // x node-major planes
__device__ __align__(16) __half g_wp1t[256 * 1088];   // W_p1^T (n-major), fp16
__device__ __align__(16) __half g_wp2t[128 * 256];    // W_p2^T (n-major), fp16
__device__ __align__(16) __half g_wgt1[64 * 64];      // W_gc1^T (n-major), fp16
__device__ __align__(16) __half g_wgt2[64 * 64];      // W_gc2^T (n-major), fp16
__device__ double g_stats[68];
__device__ float g_scale1[17], g_shift1[17], g_scale2[17], g_shift2[17];

// ---- adjacency tables (I + A_norm) ----
__constant__ int   c_cnt[17] = {2,0,0,0,0,4,4,2,2,1,1,3,3,2,2,1,1};
__constant__ float c_w[17]   = {0.5f,0.f,0.f,0.f,0.f,0.25f,0.25f,0.5f,0.5f,1.f,1.f,
                                (1.f/3.f),(1.f/3.f),0.5f,0.5f,1.f,1.f};
__constant__ int   c_nb[17][4] = {
    {5,6,0,0},  {0,0,0,0}, {0,0,0,0}, {0,0,0,0}, {0,0,0,0},
    {7,6,11,0}, {8,5,12,0},
    {5,9,0,0},  {6,10,0,0},
    {7,0,0,0},  {8,0,0,0},
    {5,12,13,0},{6,11,14,0},
    {11,15,0,0},{12,16,0,0},
    {13,0,0,0}, {14,0,0,0}
};

#define STATS_GRID 592

// ---- helpers ----
__device__ __forceinline__ uint32_t s2u(const void* p) {
    uint32_t a;
    asm("{ .reg .u64 t; cvta.to.shared.u64 t, %1; cvt.u32.u64 %0, t; }" : "=r"(a) : "l"(p));
    return a;
}
__device__ __forceinline__ uint32_t lds32(uint32_t addr) {
    uint32_t v;
    asm volatile("ld.shared.b32 %0, [%1];" : "=r"(v) : "r"(addr));
    return v;
}
// XOR swizzle on 16B chunks for 64B rows (k_pmma layout).
__device__ __forceinline__ uint32_t swz(int row, int chunk) {
    return (uint32_t)(row * 64 + ((chunk ^ ((row >> 1) & 3)) << 4));
}
#define MMA_F16(acc, a0, a1, a2, a3, b0, b1) \
    asm volatile( \
        "mma.sync.aligned.m16n8k16.row.col.f32.f16.f16.f32 " \
        "{%0,%1,%2,%3}, {%4,%5,%6,%7}, {%8,%9}, {%0,%1,%2,%3};" \
        : "+f"(acc[0]), "+f"(acc[1]), "+f"(acc[2]), "+f"(acc[3]) \
        : "r"(a0), "r"(a1), "r"(a2), "r"(a3), "r"(b0), "r"(b1))

// ---- merged prep: stats zero + 4 weight transposes + x transpose ----
// blocks [0,1088): W_p1^T; [1088,1216): W_p2^T; [1216,1232): wgt1;
// [1232,1248): wgt2; 1248: zero stats; [1249, 1249+xblocks): x -> node-major planes.
__global__ void __launch_bounds__(256)
k_prep(const float* __restrict__ Wp1, const float* __restrict__ Wp2,
       const float* __restrict__ Wg1, const float* __restrict__ Wg2,
       const float* __restrict__ x,
       __half* __restrict__ Tp1, __half* __restrict__ Tp2,
       __half* __restrict__ Tg1, __half* __restrict__ Tg2,
       float* __restrict__ xt, int B) {
    int bid = blockIdx.x;
    int tid = threadIdx.x;
    if (bid < 1088) {
        int i = bid * 256 + tid;
        int k = i >> 8, n = i & 255;
        Tp1[(size_t)n * 1088 + k] = __float2half_rn(Wp1[i]);
    } else if (bid < 1216) {
        int i = (bid - 1088) * 256 + tid;
        int k = i >> 7, n = i & 127;
        Tp2[(size_t)n * 256 + k] = __float2half_rn(Wp2[i]);
    } else if (bid < 1232) {
        int i = (bid - 1216) * 256 + tid;
        int k = i >> 6, n = i & 63;
        Tg1[n * 64 + k] = __float2half_rn(Wg1[i]);
    } else if (bid < 1248) {
        int i = (bid - 1232) * 256 + tid;
        int k = i >> 6, n = i & 63;
        Tg2[n * 64 + k] = __float2half_rn(Wg2[i]);
    } else if (bid == 1248) {
        if (tid < 68) g_stats[tid] = 0.0;
    } else {
        // x transpose: i over x elements (coalesced read), scattered plane write
        int i = (bid - 1249) * 256 + tid;       // element index into x (B*34)
        if (i < B * 34) {
            int e = i / 34;
            int r = i - e * 34;
            int n = r >> 1, c = r & 1;
            xt[(size_t)n * B * 2 + (size_t)e * 2 + c] = x[i];
        }
    }
}

// ---- stats, grid-stride + register accumulation ----
// ENC=1: y1 stats from x_t planes (float, node-major); ENC=0: y2 stats from h planes (half).
template <int ENC>
__global__ void __launch_bounds__(256)
k_st(const void* __restrict__ src, const float* __restrict__ W,
     const float* __restrict__ bvec, int B, size_t B64, int set) {
    __shared__ float h_sm[8 * 1156];
    __shared__ float ss[17], qq[17];
    int tid = threadIdx.x;
    if (tid < 17) { ss[tid] = 0.f; qq[tid] = 0.f; }

    int n0i = tid >> 4;
    int n1i = (tid + 256) >> 4;    // valid for tid<16
    float sp0 = 0.f, qp0 = 0.f, sp1 = 0.f, qp1 = 0.f;

    int nG = (B + 7) / 8;
    for (int g = blockIdx.x; g < nG; g += STATS_GRID) {
        int s0 = g * 8;
        for (int idx = tid; idx < 272; idx += 256) {
            int n = idx >> 4, c4 = idx & 15;
            float4 we0, we1, be;
            if (ENC) {
                we0 = *(const float4*)(W + c4 * 4);
                we1 = *(const float4*)(W + 64 + c4 * 4);
                be = *(const float4*)(bvec + c4 * 4);
            }
#pragma unroll
            for (int s = 0; s < 8; s++) {
                int e = s0 + s;
                if (e >= B) break;
                float4 v;
                if (ENC) {
                    const float* xt = (const float*)src;
                    float2 xp = *(const float2*)(xt + (size_t)n * B * 2 + (size_t)e * 2);
                    v.x = fmaxf(fmaf(xp.x, we0.x, fmaf(xp.y, we1.x, be.x)), 0.f);
                    v.y = fmaxf(fmaf(xp.x, we0.y, fmaf(xp.y, we1.y, be.y)), 0.f);
                    v.z = fmaxf(fmaf(xp.x, we0.z, fmaf(xp.y, we1.z, be.z)), 0.f);
                    v.w = fmaxf(fmaf(xp.x, we0.w, fmaf(xp.y, we1.w, be.w)), 0.f);
                } else {
                    const __half2* hp = (const __half2*)((const __half*)src +
                                         (size_t)n * B64 + (size_t)e * 64 + c4 * 4);
                    float2 f0 = __half22float2(hp[0]);
                    float2 f1 = __half22float2(hp[1]);
                    v = make_float4(f0.x, f0.y, f1.x, f1.y);
                }
                *(float4*)&h_sm[s * 1156 + n * 68 + c4 * 4] = v;
            }
        }
        __syncthreads();
        {
            int n = n0i, c4 = tid & 15;
            float w = c_w[n];
            int cnt = c_cnt[n];
#pragma unroll
            for (int s = 0; s < 8; s++) {
                int e = s0 + s;
                if (e >= B) break;
                float4 acc = *(const float4*)&h_sm[s * 1156 + n * 68 + c4 * 4];
                for (int j = 0; j < cnt; j++) {
                    const float4 hb = *(const float4*)&h_sm[s * 1156 + c_nb[n][j] * 68 + c4 * 4];
                    acc.x = fmaf(w, hb.x, acc.x);
                    acc.y = fmaf(w, hb.y, acc.y);
                    acc.z = fmaf(w, hb.z, acc.z);
                    acc.w = fmaf(w, hb.w, acc.w);
                }
                sp0 += acc.x + acc.y + acc.z + acc.w;
                qp0 = fmaf(acc.x, acc.x, fmaf(acc.y, acc.y, fmaf(acc.z, acc.z, fmaf(acc.w, acc.w, qp0))));
            }
        }
        if (tid < 16) {
            int n = n1i, c4 = tid & 15;
            float w = c_w[n];
            int cnt = c_cnt[n];
#pragma unroll
            for (int s = 0; s < 8; s++) {
                int e = s0 + s;
                if (e >= B) break;
                float4 acc = *(const float4*)&h_sm[s * 1156 + n * 68 + c4 * 4];
                for (int j = 0; j < cnt; j++) {
                    const float4 hb = *(const float4*)&h_sm[s * 1156 + c_nb[n][j] * 68 + c4 * 4];
                    acc.x = fmaf(w, hb.x, acc.x);
                    acc.y = fmaf(w, hb.y, acc.y);
                    acc.z = fmaf(w, hb.z, acc.z);
                    acc.w = fmaf(w, hb.w, acc.w);
                }
                sp1 += acc.x + acc.y + acc.z + acc.w;
                qp1 = fmaf(acc.x, acc.x, fmaf(acc.y, acc.y, fmaf(acc.z, acc.z, fmaf(acc.w, acc.w, qp1))));
            }
        }
        __syncthreads();
    }

    atomicAdd(&ss[n0i], sp0);
    atomicAdd(&qq[n0i], qp0);
    if (tid < 16) {
        atomicAdd(&ss[n1i], sp1);
        atomicAdd(&qq[n1i], qp1);
    }
    __syncthreads();
    if (tid < 17) {
        atomicAdd(&g_stats[set * 34 + 2 * tid], (double)ss[tid]);
        atomicAdd(&g_stats[set * 34 + 2 * tid + 1], (double)qq[tid]);
    }
}

// ---- finalize BN stats -> fused scale/shift ----
__global__ void k_fin(const float* __restrict__ gamma, const float* __restrict__ beta,
                      double invN, int set) {
    int i = threadIdx.x;
    if (i >= 17) return;
    double s = g_stats[set * 34 + 2 * i];
    double q = g_stats[set * 34 + 2 * i + 1];
    double mean = s * invN;
    double var = q * invN - mean * mean;
    if (var < 0.0) var = 0.0;
    float inv = (float)(1.0 / sqrt(var + 1e-5));
    float sc = gamma[i] * inv;
    float sh = beta[i] - (float)mean * sc;
    if (set == 0) { g_scale1[i] = sc; g_shift1[i] = sh; }
    else          { g_scale2[i] = sc; g_shift2[i] = sh; }
}

// ---- fused gc layer, node-major, fp16 mma ----
// LAYER=1: src = x_t (float, node-major planes (17,B,2)); h = relu(enc(x)).
// LAYER=2: src = h2 (half, node-major planes).
template <int LAYER>
__global__ void __launch_bounds__(256)
k_gc(const void* __restrict__ src, const float* __restrict__ Wenc,
     const float* __restrict__ benc, const __half* __restrict__ Wt,
     const float* __restrict__ bias, __half* __restrict__ C, size_t B64) {
    __shared__ __half As[128 * 88];
    __shared__ __half Ws[64 * 88];
    const int tid = threadIdx.x;
    const int w = tid >> 5, lane = tid & 31;
    const int gid = lane >> 2, tig = lane & 3;
    const int node = blockIdx.x;
    const size_t b0 = (size_t)blockIdx.y * 128;
    const int wm = (w >> 1) * 32, wn = (w & 1) * 32;
    const float sc = (LAYER == 1) ? g_scale1[node] : g_scale2[node];
    const float sh = (LAYER == 1) ? g_shift1[node] : g_shift2[node];
    const int cnt = c_cnt[node];
    const float wgt = c_w[node];
    const size_t B2 = B64 >> 5;   // B*2

#pragma unroll
    for (int it = 0; it < 4; it++) {
        int u = tid + it * 256;
        int row = u >> 3, seg = u & 7;
        size_t b = b0 + row;
        float vals[8];
        if (LAYER == 1) {
            const float* xt = (const float*)src;
            float4 w0a = *(const float4*)(Wenc + seg * 8);
            float4 w0b = *(const float4*)(Wenc + seg * 8 + 4);
            float4 w1a = *(const float4*)(Wenc + 64 + seg * 8);
            float4 w1b = *(const float4*)(Wenc + 64 + seg * 8 + 4);
            float4 bea = *(const float4*)(benc + seg * 8);
            float4 beb = *(const float4*)(benc + seg * 8 + 4);
            float2 xp = *(const float2*)(xt + (size_t)node * B2 + b * 2);
            vals[0] = fmaxf(fmaf(xp.x, w0a.x, fmaf(xp.y, w1a.x, bea.x)), 0.f);
            vals[1] = fmaxf(fmaf(xp.x, w0a.y, fmaf(xp.y, w1a.y, bea.y)), 0.f);
            vals[2] = fmaxf(fmaf(xp.x, w0a.z, fmaf(xp.y, w1a.z, bea.z)), 0.f);
            vals[3] = fmaxf(fmaf(xp.x, w0a.w, fmaf(xp.y, w1a.w, bea.w)), 0.f);
            vals[4] = fmaxf(fmaf(xp.x, w0b.x, fmaf(xp.y, w1b.x, beb.x)), 0.f);
            vals[5] = fmaxf(fmaf(xp.x, w0b.y, fmaf(xp.y, w1b.y, beb.y)), 0.f);
            vals[6] = fmaxf(fmaf(xp.x, w0b.z, fmaf(xp.y, w1b.z, beb.z)), 0.f);
            vals[7] = fmaxf(fmaf(xp.x, w0b.w, fmaf(xp.y, w1b.w, beb.w)), 0.f);
            for (int j = 0; j < cnt; j++) {
                float2 xn = *(const float2*)(xt + (size_t)c_nb[node][j] * B2 + b * 2);
                vals[0] += wgt * fmaxf(fmaf(xn.x, w0a.x, fmaf(xn.y, w1a.x, bea.x)), 0.f);
                vals[1] += wgt * fmaxf(fmaf(xn.x, w0a.y, fmaf(xn.y, w1a.y, bea.y)), 0.f);
                vals[2] += wgt * fmaxf(fmaf(xn.x, w0a.z, fmaf(xn.y, w1a.z, bea.z)), 0.f);
                vals[3] += wgt * fmaxf(fmaf(xn.x, w0a.w, fmaf(xn.y, w1a.w, bea.w)), 0.f);
                vals[4] += wgt * fmaxf(fmaf(xn.x, w0b.x, fmaf(xn.y, w1b.x, beb.x)), 0.f);
                vals[5] += wgt * fmaxf(fmaf(xn.x, w0b.y, fmaf(xn.y, w1b.y, beb.y)), 0.f);
                vals[6] += wgt * fmaxf(fmaf(xn.x, w0b.z, fmaf(xn.y, w1b.z, beb.z)), 0.f);
                vals[7] += wgt * fmaxf(fmaf(xn.x, w0b.w, fmaf(xn.y, w1b.w, beb.w)), 0.f);
            }
        } else {
            const __half* h = (const __half*)src;
            uint4 raw = *(const uint4*)(h + (size_t)node * B64 + b * 64 + seg * 8);
            const __half2* rp = (const __half2*)&raw;
#pragma unroll
            for (int p = 0; p < 4; p++) {
                float2 f = __half22float2(rp[p]);
                vals[2 * p] = f.x; vals[2 * p + 1] = f.y;
            }
            for (int j = 0; j < cnt; j++) {
                uint4 rn = *(const uint4*)(h + (size_t)c_nb[node][j] * B64 + b * 64 + seg * 8);
                const __half2* np = (const __half2*)&rn;
#pragma unroll
                for (int p = 0; p < 4; p++) {
                    float2 f = __half22float2(np[p]);
                    vals[2 * p] = fmaf(wgt, f.x, vals[2 * p]);
                    vals[2 * p + 1] = fmaf(wgt, f.y, vals[2 * p + 1]);
                }
            }
        }
        __half2 hv[4];
#pragma unroll
        for (int p = 0; p < 4; p++)
            hv[p] = __floats2half2_rn(fmaf(vals[2 * p], sc, sh), fmaf(vals[2 * p + 1], sc, sh));
        *(uint4*)&As[row * 88 + seg * 8] = *(uint4*)hv;
    }
#pragma unroll
    for (int it = 0; it < 2; it++) {
        int u = tid + it * 256;
        int row = u >> 3, seg = u & 7;
        *(uint4*)&Ws[row * 88 + seg * 8] = *(const uint4*)(Wt + row * 64 + seg * 8);
    }
    __syncthreads();

    float acc[2][4][4];
#pragma unroll
    for (int mi = 0; mi < 2; mi++)
#pragma unroll
        for (int ni = 0; ni < 4; ni++)
#pragma unroll
            for (int r = 0; r < 4; r++) acc[mi][ni][r] = 0.f;

#pragma unroll
    for (int ks = 0; ks < 4; ks++) {
        uint32_t af[2][4], bf[4][2];
#pragma unroll
        for (int mi = 0; mi < 2; mi++) {
            int rm = wm + mi * 16 + gid;
            af[mi][0] = *(const uint32_t*)&As[rm * 88 + ks * 16 + tig * 2];
            af[mi][1] = *(const uint32_t*)&As[(rm + 8) * 88 + ks * 16 + tig * 2];
            af[mi][2] = *(const uint32_t*)&As[rm * 88 + ks * 16 + 8 + tig * 2];
            af[mi][3] = *(const uint32_t*)&As[(rm + 8) * 88 + ks * 16 + 8 + tig * 2];
        }
#pragma unroll
        for (int ni = 0; ni < 4; ni++) {
            int rn = wn + ni * 8 + gid;
            bf[ni][0] = *(const uint32_t*)&Ws[rn * 88 + ks * 16 + tig * 2];
            bf[ni][1] = *(const uint32_t*)&Ws[rn * 88 + ks * 16 + 8 + tig * 2];
        }
#pragma unroll
        for (int mi = 0; mi < 2; mi++)
#pragma unroll
            for (int ni = 0; ni < 4; ni++)
                MMA_F16(acc[mi][ni], af[mi][0], af[mi][1], af[mi][2], af[mi][3],
                        bf[ni][0], bf[ni][1]);
    }

#pragma unroll
    for (int mi = 0; mi < 2; mi++) {
        size_t row = b0 + wm + mi * 16 + gid;
#pragma unroll
        for (int ni = 0; ni < 4; ni++) {
            int col = wn + ni * 8 + tig * 2;
            float bb0 = __ldg(bias + col), bb1 = __ldg(bias + col + 1);
            float r00 = fmaxf(acc[mi][ni][0] + bb0, 0.f);
            float r01 = fmaxf(acc[mi][ni][1] + bb1, 0.f);
            float r10 = fmaxf(acc[mi][ni][2] + bb0, 0.f);
            float r11 = fmaxf(acc[mi][ni][3] + bb1, 0.f);
            *(__half2*)(C + (size_t)node * B64 + row * 64 + col) = __floats2half2_rn(r00, r01);
            *(__half2*)(C + (size_t)node * B64 + (row + 8) * 64 + col) = __floats2half2_rn(r10, r11);
        }
    }
}

// ---- pool GEMM via fp16 mma (m16n8k16) ----
#define PH_STAGE 16384
#define PH_SMEM (2 * PH_STAGE)
template <int KDIM, int CN, int RELU, int OUTHALF, int NORM, int NODEMAJ>
__global__ void __launch_bounds__(256)
k_pmma(const __half* __restrict__ A, const __half* __restrict__ Bt,
       const float* __restrict__ bias, void* __restrict__ Cout, size_t B64) {
    extern __shared__ float smf[];
    const uint32_t sb = s2u(smf);
    const int tid = threadIdx.x;
    const int w = tid >> 5, lane = tid & 31;
    const int gid = lane >> 2, tig = lane & 3;
    const size_t m0 = (size_t)blockIdx.y * 128;
    const int n0 = blockIdx.x * 128;
    const int wm = (w >> 2) * 64, wn = (w & 3) * 32;
    const int NCH = KDIM / 32;

    float acc[4][4][4];
#pragma unroll
    for (int mi = 0; mi < 4; mi++)
#pragma unroll
        for (int ni = 0; ni < 4; ni++)
#pragma unroll
            for (int r = 0; r < 4; r++) acc[mi][ni][r] = 0.f;

    auto load_chunk = [&](int c, int s) {
        uint32_t base = sb + (uint32_t)s * PH_STAGE;
        int kc = c * 32;
#pragma unroll
        for (int j = 0; j < 2; j++) {
            int u = tid + j * 256;
            int row = u >> 2, cc = u & 3;
            const __half* src;
            if (NODEMAJ) {
                int kk = kc + cc * 8;
                int nd = kk >> 6, ko = kk & 63;
                src = A + (size_t)nd * B64 + (m0 + row) * 64 + ko;
            } else {
                src = A + (m0 + row) * (size_t)KDIM + kc + cc * 8;
            }
            uint32_t d = base + swz(row, cc);
            asm volatile("cp.async.cg.shared.global [%0], [%1], 16;" :: "r"(d), "l"(src) : "memory");
        }
#pragma unroll
        for (int j = 0; j < 2; j++) {
            int u = tid + j * 256;
            int row = u >> 2, cc = u & 3;
            const __half* src = Bt + (size_t)(n0 + row) * KDIM + kc + cc * 8;
            uint32_t d = base + 8192 + swz(row, cc);
            asm volatile("cp.async.cg.shared.global [%0], [%1], 16;" :: "r"(d), "l"(src) : "memory");
        }
        asm volatile("cp.async.commit_group;" ::: "memory");
    };

    load_chunk(0, 0);
    if (NCH > 1) load_chunk(1, 1);

    for (int c = 0; c < NCH; c++) {
        int s = c & 1;
        if (c == NCH - 1) asm volatile("cp.async.wait_group 0;" ::: "memory");
        else              asm volatile("cp.async.wait_group 1;" ::: "memory");
        __syncthreads();
        uint32_t baseA = sb + (uint32_t)s * PH_STAGE;
        uint32_t baseB = baseA + 8192;
#pragma unroll
        for (int ks = 0; ks < 2; ks++) {
            int c0 = 2 * ks, c1 = 2 * ks + 1;
            uint32_t af[4][4], bf[4][2];
#pragma unroll
            for (int mi = 0; mi < 4; mi++) {
                int r0 = wm + mi * 16 + gid, r1 = r0 + 8;
                af[mi][0] = lds32(baseA + swz(r0, c0) + tig * 4);
                af[mi][1] = lds32(baseA + swz(r1, c0) + tig * 4);
                af[mi][2] = lds32(baseA + swz(r0, c1) + tig * 4);
                af[mi][3] = lds32(baseA + swz(r1, c1) + tig * 4);
            }
#pragma unroll
            for (int ni = 0; ni < 4; ni++) {
                int rn = wn + ni * 8 + gid;
                bf[ni][0] = lds32(baseB + swz(rn, c0) + tig * 4);
                bf[ni][1] = lds32(baseB + swz(rn, c1) + tig * 4);
            }
#pragma unroll
            for (int mi = 0; mi < 4; mi++)
#pragma unroll
                for (int ni = 0; ni < 4; ni++)
                    MMA_F16(acc[mi][ni], af[mi][0], af[mi][1], af[mi][2], af[mi][3],
                            bf[ni][0], bf[ni][1]);
        }
        __syncthreads();
        if (c + 2 < NCH) load_chunk(c + 2, s);
    }

#pragma unroll
    for (int mi = 0; mi < 4; mi++)
#pragma unroll
        for (int ni = 0; ni < 4; ni++) {
            int col = n0 + wn + ni * 8 + tig * 2;
            float b0 = __ldg(bias + col), b1 = __ldg(bias + col + 1);
            acc[mi][ni][0] += b0; acc[mi][ni][1] += b1;
            acc[mi][ni][2] += b0; acc[mi][ni][3] += b1;
            if (RELU) {
#pragma unroll
                for (int r = 0; r < 4; r++) acc[mi][ni][r] = fmaxf(acc[mi][ni][r], 0.f);
            }
        }

    float rs[4][2];
    if (NORM) {
        float* rowssq = smf;
        for (int i = tid; i < 128; i += 256) rowssq[i] = 0.f;
        __syncthreads();
#pragma unroll
        for (int mi = 0; mi < 4; mi++) {
            float p0 = 0.f, p1 = 0.f;
#pragma unroll
            for (int ni = 0; ni < 4; ni++) {
                p0 = fmaf(acc[mi][ni][0], acc[mi][ni][0], fmaf(acc[mi][ni][1], acc[mi][ni][1], p0));
                p1 = fmaf(acc[mi][ni][2], acc[mi][ni][2], fmaf(acc[mi][ni][3], acc[mi][ni][3], p1));
            }
            atomicAdd(&rowssq[wm + mi * 16 + gid], p0);
            atomicAdd(&rowssq[wm + mi * 16 + gid + 8], p1);
        }
        __syncthreads();
#pragma unroll
        for (int mi = 0; mi < 4; mi++) {
            rs[mi][0] = 1.f / fmaxf(sqrtf(rowssq[wm + mi * 16 + gid]), 1e-12f);
            rs[mi][1] = 1.f / fmaxf(sqrtf(rowssq[wm + mi * 16 + gid + 8]), 1e-12f);
        }
    }

#pragma unroll
    for (int mi = 0; mi < 4; mi++) {
        size_t row = m0 + wm + mi * 16 + gid;
#pragma unroll
        for (int ni = 0; ni < 4; ni++) {
            int col = n0 + wn + ni * 8 + tig * 2;
            float v00 = acc[mi][ni][0], v01 = acc[mi][ni][1];
            float v10 = acc[mi][ni][2], v11 = acc[mi][ni][3];
            if (NORM) {
                v00 *= rs[mi][0]; v01 *= rs[mi][0];
                v10 *= rs[mi][1]; v11 *= rs[mi][1];
            }
            if (OUTHALF) {
                __half* Ch = (__half*)Cout;
                *(__half2*)(Ch + row * CN + col) = __floats2half2_rn(v00, v01);
                *(__half2*)(Ch + (row + 8) * CN + col) = __floats2half2_rn(v10, v11);
            } else {
                float* Cf = (float*)Cout;
                *(float2*)(Cf + row * CN + col) = make_float2(v00, v01);
                *(float2*)(Cf + (row + 8) * CN + col) = make_float2(v10, v11);
            }
        }
    }
}

extern "C" void kernel_launch(void* const* d_in, const int* in_sizes, int n_in,
                              void* d_out, int out_size) {
    const float* x      = (const float*)d_in[0];
    const float* W_enc  = (const float*)d_in[1];
    const float* b_enc  = (const float*)d_in[2];
    const float* W_gc1  = (const float*)d_in[3];
    const float* b_gc1  = (const float*)d_in[4];
    const float* W_gc2  = (const float*)d_in[5];
    const float* b_gc2  = (const float*)d_in[6];
    const float* gamma1 = (const float*)d_in[7];
    const float* beta1  = (const float*)d_in[8];
    const float* gamma2 = (const float*)d_in[9];
    const float* beta2  = (const float*)d_in[10];
    const float* W_p1   = (const float*)d_in[11];
    const float* b_p1   = (const float*)d_in[12];
    const float* W_p2   = (const float*)d_in[13];
    const float* b_p2   = (const float*)d_in[14];
    float* out = (float*)d_out;

    // Resolve device addresses of __device__ globals (host shadow != device ptr).
    __half *bufA = 0, *bufB = 0, *z = 0, *wp1t = 0, *wp2t = 0, *wgt1 = 0, *wgt2 = 0;
    float *xt = 0;
    cudaGetSymbolAddress((void**)&bufA, g_bufA);
    cudaGetSymbolAddress((void**)&bufB, g_bufB);
    cudaGetSymbolAddress((void**)&z,    g_z);
    cudaGetSymbolAddress((void**)&xt,   g_xt);
    cudaGetSymbolAddress((void**)&wp1t, g_wp1t);
    cudaGetSymbolAddress((void**)&wp2t, g_wp2t);
    cudaGetSymbolAddress((void**)&wgt1, g_wgt1);
    cudaGetSymbolAddress((void**)&wgt2, g_wgt2);

    cudaFuncSetAttribute((const void*)k_pmma<1088, 256, 1, 1, 0, 1>,
                         cudaFuncAttributeMaxDynamicSharedMemorySize, PH_SMEM);
    cudaFuncSetAttribute((const void*)k_pmma<256, 128, 0, 0, 1, 0>,
                         cudaFuncAttributeMaxDynamicSharedMemorySize, PH_SMEM);

    int B = in_sizes[0] / 34;        // x is (B,17,2)
    if (B <= 0) return;
    size_t B64 = (size_t)B * 64;
    double invN = 1.0 / ((double)B * 64.0);
    int xblocks = (B * 34 + 255) / 256;

    // merged prep: stats zero + 4 weight transposes + x -> node-major planes
    k_prep<<<1249 + xblocks, 256>>>(W_p1, W_p2, W_gc1, W_gc2, x,
                                    wp1t, wp2t, wgt1, wgt2, xt, B);
    // BN1 stats from x_t planes
    k_st<1><<<STATS_GRID, 256>>>(xt, W_enc, b_enc, B, 0, 0);
    k_fin<<<1, 32>>>(gamma1, beta1, invN, 0);
    // gc1 fused enc+agg+BN1+GEMM -> h2 planes (node-major, fp16) in bufB
    k_gc<1><<<dim3(17, B / 128), 256>>>(xt, W_enc, b_enc, wgt1, b_gc1, bufB, B64);
    // BN2 stats from h2 planes
    k_st<0><<<STATS_GRID, 256>>>(bufB, 0, 0, B, B64, 1);
    k_fin<<<1, 32>>>(gamma2, beta2, invN, 1);
    // gc2 fused agg+BN2+GEMM -> pooled planes (node-major, fp16) in bufA
    k_gc<2><<<dim3(17, B / 128), 256>>>(bufB, 0, 0, wgt2, b_gc2, bufA, B64);
    // p1 (fp16 mma, node-major A gather): z = relu(pooled @ W_p1 + b_p1) -> z (B,256)
    k_pmma<1088, 256, 1, 1, 0, 1><<<dim3(2, B / 128), 256, PH_SMEM>>>(bufA, wp1t, b_p1, z, B64);
    // p2 (fp16 mma) + fused L2 normalize -> out (B,128) fp32
    k_pmma<256, 128, 0, 0, 1, 0><<<dim3(1, B / 128), 256, PH_SMEM>>>(z, wp2t, b_p2, out, 0);
}

// round 17
// speedup vs baseline: 1.4666x; 1.4666x over previous
#include <cuda_runtime.h>
#include <cuda_fp16.h>
#include <math.h>
#include <stdint.h>

#define BMAX 65536

// ---- scratch (allocation-free rule: __device__ globals) ----
// bufA/bufB hold node-major activations: plane n at n*B64, element (n,b,c) at n*B64+b*64+c.
__device__ __align__(16) __half g_bufA[(size_t)BMAX * 17 * 64];
__device__ __align__(16) __half g_bufB[(size_t)BMAX * 17 * 64];
__device__ __align__(16) __half g_z[(size_t)BMAX * 256];
__device__ __align__(16) __half g_wp1t[256 * 1088];   // W_p1^T (n-major), fp16
__device__ __align__(16) __half g_wp2t[128 * 256];    // W_p2^T (n-major), fp16
__device__ __align__(16) __half g_wgt1[64 * 64];      // W_gc1^T (n-major), fp16
__device__ __align__(16) __half g_wgt2[64 * 64];      // W_gc2^T (n-major), fp16
__device__ double g_stats[68];
__device__ float g_scale1[17], g_shift1[17], g_scale2[17], g_shift2[17];

// ---- adjacency tables (I + A_norm) ----
__constant__ int   c_cnt[17] = {2,0,0,0,0,4,4,2,2,1,1,3,3,2,2,1,1};
__constant__ float c_w[17]   = {0.5f,0.f,0.f,0.f,0.f,0.25f,0.25f,0.5f,0.5f,1.f,1.f,
                                (1.f/3.f),(1.f/3.f),0.5f,0.5f,1.f,1.f};
__constant__ int   c_nb[17][4] = {
    {5,6,0,0},  {0,0,0,0}, {0,0,0,0}, {0,0,0,0}, {0,0,0,0},
    {7,6,11,0}, {8,5,12,0},
    {5,9,0,0},  {6,10,0,0},
    {7,0,0,0},  {8,0,0,0},
    {5,12,13,0},{6,11,14,0},
    {11,15,0,0},{12,16,0,0},
    {13,0,0,0}, {14,0,0,0}
};

#define STATS_GRID 592

// ---- helpers ----
__device__ __forceinline__ uint32_t s2u(const void* p) {
    uint32_t a;
    asm("{ .reg .u64 t; cvta.to.shared.u64 t, %1; cvt.u32.u64 %0, t; }" : "=r"(a) : "l"(p));
    return a;
}
__device__ __forceinline__ uint32_t lds32(uint32_t addr) {
    uint32_t v;
    asm volatile("ld.shared.b32 %0, [%1];" : "=r"(v) : "r"(addr));
    return v;
}
// XOR swizzle on 16B chunks for 64B rows (k_pmma layout).
__device__ __forceinline__ uint32_t swz(int row, int chunk) {
    return (uint32_t)(row * 64 + ((chunk ^ ((row >> 1) & 3)) << 4));
}
#define MMA_F16(acc, a0, a1, a2, a3, b0, b1) \
    asm volatile( \
        "mma.sync.aligned.m16n8k16.row.col.f32.f16.f16.f32 " \
        "{%0,%1,%2,%3}, {%4,%5,%6,%7}, {%8,%9}, {%0,%1,%2,%3};" \
        : "+f"(acc[0]), "+f"(acc[1]), "+f"(acc[2]), "+f"(acc[3]) \
        : "r"(a0), "r"(a1), "r"(a2), "r"(a3), "r"(b0), "r"(b1))

// ---- merged prep: stats zero + 4 weight transposes (R15 winner form) ----
__global__ void __launch_bounds__(256)
k_prep(const float* __restrict__ Wp1, const float* __restrict__ Wp2,
       const float* __restrict__ Wg1, const float* __restrict__ Wg2,
       __half* __restrict__ Tp1, __half* __restrict__ Tp2,
       __half* __restrict__ Tg1, __half* __restrict__ Tg2) {
    int bid = blockIdx.x;
    int tid = threadIdx.x;
    if (bid < 1088) {
        int i = bid * 256 + tid;
        int k = i >> 8, n = i & 255;
        Tp1[(size_t)n * 1088 + k] = __float2half_rn(Wp1[i]);
    } else if (bid < 1216) {
        int i = (bid - 1088) * 256 + tid;
        int k = i >> 7, n = i & 127;
        Tp2[(size_t)n * 256 + k] = __float2half_rn(Wp2[i]);
    } else if (bid < 1232) {
        int i = (bid - 1216) * 256 + tid;
        int k = i >> 6, n = i & 63;
        Tg1[n * 64 + k] = __float2half_rn(Wg1[i]);
    } else if (bid < 1248) {
        int i = (bid - 1232) * 256 + tid;
        int k = i >> 6, n = i & 63;
        Tg2[n * 64 + k] = __float2half_rn(Wg2[i]);
    } else {
        if (tid < 68) g_stats[tid] = 0.0;
    }
}

// ---- stats, grid-stride + register accumulation (R15 winner form) ----
// ENC=1: y1 stats from x (float, sample-major); ENC=0: y2 stats from h planes (half).
template <int ENC>
__global__ void __launch_bounds__(256)
k_st(const void* __restrict__ src, const float* __restrict__ W,
     const float* __restrict__ bvec, int B, size_t B64, int set) {
    __shared__ float h_sm[8 * 1156];
    __shared__ float ss[17], qq[17];
    int tid = threadIdx.x;
    if (tid < 17) { ss[tid] = 0.f; qq[tid] = 0.f; }

    int n0i = tid >> 4;
    int n1i = (tid + 256) >> 4;    // valid for tid<16
    float sp0 = 0.f, qp0 = 0.f, sp1 = 0.f, qp1 = 0.f;

    int nG = (B + 7) / 8;
    for (int g = blockIdx.x; g < nG; g += STATS_GRID) {
        int s0 = g * 8;
        for (int idx = tid; idx < 272; idx += 256) {
            int n = idx >> 4, c4 = idx & 15;
            float4 we0, we1, be;
            if (ENC) {
                we0 = *(const float4*)(W + c4 * 4);
                we1 = *(const float4*)(W + 64 + c4 * 4);
                be = *(const float4*)(bvec + c4 * 4);
            }
#pragma unroll
            for (int s = 0; s < 8; s++) {
                int e = s0 + s;
                if (e >= B) break;
                float4 v;
                if (ENC) {
                    const float* xf = (const float*)src;
                    float x0 = xf[((size_t)e * 17 + n) * 2];
                    float x1 = xf[((size_t)e * 17 + n) * 2 + 1];
                    v.x = fmaxf(fmaf(x0, we0.x, fmaf(x1, we1.x, be.x)), 0.f);
                    v.y = fmaxf(fmaf(x0, we0.y, fmaf(x1, we1.y, be.y)), 0.f);
                    v.z = fmaxf(fmaf(x0, we0.z, fmaf(x1, we1.z, be.z)), 0.f);
                    v.w = fmaxf(fmaf(x0, we0.w, fmaf(x1, we1.w, be.w)), 0.f);
                } else {
                    const __half2* hp = (const __half2*)((const __half*)src +
                                         (size_t)n * B64 + (size_t)e * 64 + c4 * 4);
                    float2 f0 = __half22float2(hp[0]);
                    float2 f1 = __half22float2(hp[1]);
                    v = make_float4(f0.x, f0.y, f1.x, f1.y);
                }
                *(float4*)&h_sm[s * 1156 + n * 68 + c4 * 4] = v;
            }
        }
        __syncthreads();
        {
            int n = n0i, c4 = tid & 15;
            float w = c_w[n];
            int cnt = c_cnt[n];
#pragma unroll
            for (int s = 0; s < 8; s++) {
                int e = s0 + s;
                if (e >= B) break;
                float4 acc = *(const float4*)&h_sm[s * 1156 + n * 68 + c4 * 4];
                for (int j = 0; j < cnt; j++) {
                    const float4 hb = *(const float4*)&h_sm[s * 1156 + c_nb[n][j] * 68 + c4 * 4];
                    acc.x = fmaf(w, hb.x, acc.x);
                    acc.y = fmaf(w, hb.y, acc.y);
                    acc.z = fmaf(w, hb.z, acc.z);
                    acc.w = fmaf(w, hb.w, acc.w);
                }
                sp0 += acc.x + acc.y + acc.z + acc.w;
                qp0 = fmaf(acc.x, acc.x, fmaf(acc.y, acc.y, fmaf(acc.z, acc.z, fmaf(acc.w, acc.w, qp0))));
            }
        }
        if (tid < 16) {
            int n = n1i, c4 = tid & 15;
            float w = c_w[n];
            int cnt = c_cnt[n];
#pragma unroll
            for (int s = 0; s < 8; s++) {
                int e = s0 + s;
                if (e >= B) break;
                float4 acc = *(const float4*)&h_sm[s * 1156 + n * 68 + c4 * 4];
                for (int j = 0; j < cnt; j++) {
                    const float4 hb = *(const float4*)&h_sm[s * 1156 + c_nb[n][j] * 68 + c4 * 4];
                    acc.x = fmaf(w, hb.x, acc.x);
                    acc.y = fmaf(w, hb.y, acc.y);
                    acc.z = fmaf(w, hb.z, acc.z);
                    acc.w = fmaf(w, hb.w, acc.w);
                }
                sp1 += acc.x + acc.y + acc.z + acc.w;
                qp1 = fmaf(acc.x, acc.x, fmaf(acc.y, acc.y, fmaf(acc.z, acc.z, fmaf(acc.w, acc.w, qp1))));
            }
        }
        __syncthreads();
    }

    atomicAdd(&ss[n0i], sp0);
    atomicAdd(&qq[n0i], qp0);
    if (tid < 16) {
        atomicAdd(&ss[n1i], sp1);
        atomicAdd(&qq[n1i], qp1);
    }
    __syncthreads();
    if (tid < 17) {
        atomicAdd(&g_stats[set * 34 + 2 * tid], (double)ss[tid]);
        atomicAdd(&g_stats[set * 34 + 2 * tid + 1], (double)qq[tid]);
    }
}

// ---- finalize BN stats -> fused scale/shift ----
__global__ void k_fin(const float* __restrict__ gamma, const float* __restrict__ beta,
                      double invN, int set) {
    int i = threadIdx.x;
    if (i >= 17) return;
    double s = g_stats[set * 34 + 2 * i];
    double q = g_stats[set * 34 + 2 * i + 1];
    double mean = s * invN;
    double var = q * invN - mean * mean;
    if (var < 0.0) var = 0.0;
    float inv = (float)(1.0 / sqrt(var + 1e-5));
    float sc = gamma[i] * inv;
    float sh = beta[i] - (float)mean * sc;
    if (set == 0) { g_scale1[i] = sc; g_shift1[i] = sh; }
    else          { g_scale2[i] = sc; g_shift2[i] = sh; }
}

// ---- fused gc layer, node-major, fp16 mma ----
// LAYER=1: src = x (float, sample-major (B,17,2)), STAGED into smem first
//          (contiguous 17.4KB tile, fully coalesced), h = relu(enc(x)).
// LAYER=2: src = h2 (half, node-major planes).
// Dynamic smem: LAYER=1: xs[4352]f + As + Ws = 51200B; LAYER=2: As + Ws = 33792B.
#define GC1_SMEM (4352 * 4 + 128 * 88 * 2 + 64 * 88 * 2)
#define GC2_SMEM (128 * 88 * 2 + 64 * 88 * 2)
template <int LAYER>
__global__ void __launch_bounds__(256)
k_gc(const void* __restrict__ src, const float* __restrict__ Wenc,
     const float* __restrict__ benc, const __half* __restrict__ Wt,
     const float* __restrict__ bias, __half* __restrict__ C, size_t B64) {
    extern __shared__ char smraw[];
    float* xs = (float*)smraw;                      // LAYER=1 only: [128][34]
    __half* As = (LAYER == 1) ? (__half*)(smraw + 4352 * 4) : (__half*)smraw;
    __half* Ws = As + 128 * 88;
    const int tid = threadIdx.x;
    const int w = tid >> 5, lane = tid & 31;
    const int gid = lane >> 2, tig = lane & 3;
    const int node = blockIdx.x;
    const size_t b0 = (size_t)blockIdx.y * 128;
    const int wm = (w >> 1) * 32, wn = (w & 1) * 32;
    const float sc = (LAYER == 1) ? g_scale1[node] : g_scale2[node];
    const float sh = (LAYER == 1) ? g_shift1[node] : g_shift2[node];
    const int cnt = c_cnt[node];
    const float wgt = c_w[node];

    if (LAYER == 1) {
        // stage x tile: rows b0..b0+127 are CONTIGUOUS in x (4352 floats)
        const float* x = (const float*)src;
#pragma unroll
        for (int it = 0; it < 17; it++) {
            int i = tid + it * 256;
            if (i < 4352) xs[i] = x[b0 * 34 + i];
        }
        __syncthreads();
    }

#pragma unroll
    for (int it = 0; it < 4; it++) {
        int u = tid + it * 256;
        int row = u >> 3, seg = u & 7;
        size_t b = b0 + row;
        float vals[8];
        if (LAYER == 1) {
            float4 w0a = *(const float4*)(Wenc + seg * 8);
            float4 w0b = *(const float4*)(Wenc + seg * 8 + 4);
            float4 w1a = *(const float4*)(Wenc + 64 + seg * 8);
            float4 w1b = *(const float4*)(Wenc + 64 + seg * 8 + 4);
            float4 bea = *(const float4*)(benc + seg * 8);
            float4 beb = *(const float4*)(benc + seg * 8 + 4);
            float2 xp = *(const float2*)&xs[row * 34 + node * 2];
            vals[0] = fmaxf(fmaf(xp.x, w0a.x, fmaf(xp.y, w1a.x, bea.x)), 0.f);
            vals[1] = fmaxf(fmaf(xp.x, w0a.y, fmaf(xp.y, w1a.y, bea.y)), 0.f);
            vals[2] = fmaxf(fmaf(xp.x, w0a.z, fmaf(xp.y, w1a.z, bea.z)), 0.f);
            vals[3] = fmaxf(fmaf(xp.x, w0a.w, fmaf(xp.y, w1a.w, bea.w)), 0.f);
            vals[4] = fmaxf(fmaf(xp.x, w0b.x, fmaf(xp.y, w1b.x, beb.x)), 0.f);
            vals[5] = fmaxf(fmaf(xp.x, w0b.y, fmaf(xp.y, w1b.y, beb.y)), 0.f);
            vals[6] = fmaxf(fmaf(xp.x, w0b.z, fmaf(xp.y, w1b.z, beb.z)), 0.f);
            vals[7] = fmaxf(fmaf(xp.x, w0b.w, fmaf(xp.y, w1b.w, beb.w)), 0.f);
            for (int j = 0; j < cnt; j++) {
                float2 xn = *(const float2*)&xs[row * 34 + c_nb[node][j] * 2];
                vals[0] += wgt * fmaxf(fmaf(xn.x, w0a.x, fmaf(xn.y, w1a.x, bea.x)), 0.f);
                vals[1] += wgt * fmaxf(fmaf(xn.x, w0a.y, fmaf(xn.y, w1a.y, bea.y)), 0.f);
                vals[2] += wgt * fmaxf(fmaf(xn.x, w0a.z, fmaf(xn.y, w1a.z, bea.z)), 0.f);
                vals[3] += wgt * fmaxf(fmaf(xn.x, w0a.w, fmaf(xn.y, w1a.w, bea.w)), 0.f);
                vals[4] += wgt * fmaxf(fmaf(xn.x, w0b.x, fmaf(xn.y, w1b.x, beb.x)), 0.f);
                vals[5] += wgt * fmaxf(fmaf(xn.x, w0b.y, fmaf(xn.y, w1b.y, beb.y)), 0.f);
                vals[6] += wgt * fmaxf(fmaf(xn.x, w0b.z, fmaf(xn.y, w1b.z, beb.z)), 0.f);
                vals[7] += wgt * fmaxf(fmaf(xn.x, w0b.w, fmaf(xn.y, w1b.w, beb.w)), 0.f);
            }
        } else {
            const __half* h = (const __half*)src;
            uint4 raw = *(const uint4*)(h + (size_t)node * B64 + b * 64 + seg * 8);
            const __half2* rp = (const __half2*)&raw;
#pragma unroll
            for (int p = 0; p < 4; p++) {
                float2 f = __half22float2(rp[p]);
                vals[2 * p] = f.x; vals[2 * p + 1] = f.y;
            }
            for (int j = 0; j < cnt; j++) {
                uint4 rn = *(const uint4*)(h + (size_t)c_nb[node][j] * B64 + b * 64 + seg * 8);
                const __half2* np = (const __half2*)&rn;
#pragma unroll
                for (int p = 0; p < 4; p++) {
                    float2 f = __half22float2(np[p]);
                    vals[2 * p] = fmaf(wgt, f.x, vals[2 * p]);
                    vals[2 * p + 1] = fmaf(wgt, f.y, vals[2 * p + 1]);
                }
            }
        }
        __half2 hv[4];
#pragma unroll
        for (int p = 0; p < 4; p++)
            hv[p] = __floats2half2_rn(fmaf(vals[2 * p], sc, sh), fmaf(vals[2 * p + 1], sc, sh));
        *(uint4*)&As[row * 88 + seg * 8] = *(uint4*)hv;
    }
#pragma unroll
    for (int it = 0; it < 2; it++) {
        int u = tid + it * 256;
        int row = u >> 3, seg = u & 7;
        *(uint4*)&Ws[row * 88 + seg * 8] = *(const uint4*)(Wt + row * 64 + seg * 8);
    }
    __syncthreads();

    float acc[2][4][4];
#pragma unroll
    for (int mi = 0; mi < 2; mi++)
#pragma unroll
        for (int ni = 0; ni < 4; ni++)
#pragma unroll
            for (int r = 0; r < 4; r++) acc[mi][ni][r] = 0.f;

#pragma unroll
    for (int ks = 0; ks < 4; ks++) {
        uint32_t af[2][4], bf[4][2];
#pragma unroll
        for (int mi = 0; mi < 2; mi++) {
            int rm = wm + mi * 16 + gid;
            af[mi][0] = *(const uint32_t*)&As[rm * 88 + ks * 16 + tig * 2];
            af[mi][1] = *(const uint32_t*)&As[(rm + 8) * 88 + ks * 16 + tig * 2];
            af[mi][2] = *(const uint32_t*)&As[rm * 88 + ks * 16 + 8 + tig * 2];
            af[mi][3] = *(const uint32_t*)&As[(rm + 8) * 88 + ks * 16 + 8 + tig * 2];
        }
#pragma unroll
        for (int ni = 0; ni < 4; ni++) {
            int rn = wn + ni * 8 + gid;
            bf[ni][0] = *(const uint32_t*)&Ws[rn * 88 + ks * 16 + tig * 2];
            bf[ni][1] = *(const uint32_t*)&Ws[rn * 88 + ks * 16 + 8 + tig * 2];
        }
#pragma unroll
        for (int mi = 0; mi < 2; mi++)
#pragma unroll
            for (int ni = 0; ni < 4; ni++)
                MMA_F16(acc[mi][ni], af[mi][0], af[mi][1], af[mi][2], af[mi][3],
                        bf[ni][0], bf[ni][1]);
    }

#pragma unroll
    for (int mi = 0; mi < 2; mi++) {
        size_t row = b0 + wm + mi * 16 + gid;
#pragma unroll
        for (int ni = 0; ni < 4; ni++) {
            int col = wn + ni * 8 + tig * 2;
            float bb0 = __ldg(bias + col), bb1 = __ldg(bias + col + 1);
            float r00 = fmaxf(acc[mi][ni][0] + bb0, 0.f);
            float r01 = fmaxf(acc[mi][ni][1] + bb1, 0.f);
            float r10 = fmaxf(acc[mi][ni][2] + bb0, 0.f);
            float r11 = fmaxf(acc[mi][ni][3] + bb1, 0.f);
            *(__half2*)(C + (size_t)node * B64 + row * 64 + col) = __floats2half2_rn(r00, r01);
            *(__half2*)(C + (size_t)node * B64 + (row + 8) * 64 + col) = __floats2half2_rn(r10, r11);
        }
    }
}

// ---- pool GEMM via fp16 mma (m16n8k16) (unchanged R15 winner) ----
#define PH_STAGE 16384
#define PH_SMEM (2 * PH_STAGE)
template <int KDIM, int CN, int RELU, int OUTHALF, int NORM, int NODEMAJ>
__global__ void __launch_bounds__(256)
k_pmma(const __half* __restrict__ A, const __half* __restrict__ Bt,
       const float* __restrict__ bias, void* __restrict__ Cout, size_t B64) {
    extern __shared__ float smf[];
    const uint32_t sb = s2u(smf);
    const int tid = threadIdx.x;
    const int w = tid >> 5, lane = tid & 31;
    const int gid = lane >> 2, tig = lane & 3;
    const size_t m0 = (size_t)blockIdx.y * 128;
    const int n0 = blockIdx.x * 128;
    const int wm = (w >> 2) * 64, wn = (w & 3) * 32;
    const int NCH = KDIM / 32;

    float acc[4][4][4];
#pragma unroll
    for (int mi = 0; mi < 4; mi++)
#pragma unroll
        for (int ni = 0; ni < 4; ni++)
#pragma unroll
            for (int r = 0; r < 4; r++) acc[mi][ni][r] = 0.f;

    auto load_chunk = [&](int c, int s) {
        uint32_t base = sb + (uint32_t)s * PH_STAGE;
        int kc = c * 32;
#pragma unroll
        for (int j = 0; j < 2; j++) {
            int u = tid + j * 256;
            int row = u >> 2, cc = u & 3;
            const __half* src;
            if (NODEMAJ) {
                int kk = kc + cc * 8;
                int nd = kk >> 6, ko = kk & 63;
                src = A + (size_t)nd * B64 + (m0 + row) * 64 + ko;
            } else {
                src = A + (m0 + row) * (size_t)KDIM + kc + cc * 8;
            }
            uint32_t d = base + swz(row, cc);
            asm volatile("cp.async.cg.shared.global [%0], [%1], 16;" :: "r"(d), "l"(src) : "memory");
        }
#pragma unroll
        for (int j = 0; j < 2; j++) {
            int u = tid + j * 256;
            int row = u >> 2, cc = u & 3;
            const __half* src = Bt + (size_t)(n0 + row) * KDIM + kc + cc * 8;
            uint32_t d = base + 8192 + swz(row, cc);
            asm volatile("cp.async.cg.shared.global [%0], [%1], 16;" :: "r"(d), "l"(src) : "memory");
        }
        asm volatile("cp.async.commit_group;" ::: "memory");
    };

    load_chunk(0, 0);
    if (NCH > 1) load_chunk(1, 1);

    for (int c = 0; c < NCH; c++) {
        int s = c & 1;
        if (c == NCH - 1) asm volatile("cp.async.wait_group 0;" ::: "memory");
        else              asm volatile("cp.async.wait_group 1;" ::: "memory");
        __syncthreads();
        uint32_t baseA = sb + (uint32_t)s * PH_STAGE;
        uint32_t baseB = baseA + 8192;
#pragma unroll
        for (int ks = 0; ks < 2; ks++) {
            int c0 = 2 * ks, c1 = 2 * ks + 1;
            uint32_t af[4][4], bf[4][2];
#pragma unroll
            for (int mi = 0; mi < 4; mi++) {
                int r0 = wm + mi * 16 + gid, r1 = r0 + 8;
                af[mi][0] = lds32(baseA + swz(r0, c0) + tig * 4);
                af[mi][1] = lds32(baseA + swz(r1, c0) + tig * 4);
                af[mi][2] = lds32(baseA + swz(r0, c1) + tig * 4);
                af[mi][3] = lds32(baseA + swz(r1, c1) + tig * 4);
            }
#pragma unroll
            for (int ni = 0; ni < 4; ni++) {
                int rn = wn + ni * 8 + gid;
                bf[ni][0] = lds32(baseB + swz(rn, c0) + tig * 4);
                bf[ni][1] = lds32(baseB + swz(rn, c1) + tig * 4);
            }
#pragma unroll
            for (int mi = 0; mi < 4; mi++)
#pragma unroll
                for (int ni = 0; ni < 4; ni++)
                    MMA_F16(acc[mi][ni], af[mi][0], af[mi][1], af[mi][2], af[mi][3],
                            bf[ni][0], bf[ni][1]);
        }
        __syncthreads();
        if (c + 2 < NCH) load_chunk(c + 2, s);
    }

#pragma unroll
    for (int mi = 0; mi < 4; mi++)
#pragma unroll
        for (int ni = 0; ni < 4; ni++) {
            int col = n0 + wn + ni * 8 + tig * 2;
            float b0 = __ldg(bias + col), b1 = __ldg(bias + col + 1);
            acc[mi][ni][0] += b0; acc[mi][ni][1] += b1;
            acc[mi][ni][2] += b0; acc[mi][ni][3] += b1;
            if (RELU) {
#pragma unroll
                for (int r = 0; r < 4; r++) acc[mi][ni][r] = fmaxf(acc[mi][ni][r], 0.f);
            }
        }

    float rs[4][2];
    if (NORM) {
        float* rowssq = smf;
        for (int i = tid; i < 128; i += 256) rowssq[i] = 0.f;
        __syncthreads();
#pragma unroll
        for (int mi = 0; mi < 4; mi++) {
            float p0 = 0.f, p1 = 0.f;
#pragma unroll
            for (int ni = 0; ni < 4; ni++) {
                p0 = fmaf(acc[mi][ni][0], acc[mi][ni][0], fmaf(acc[mi][ni][1], acc[mi][ni][1], p0));
                p1 = fmaf(acc[mi][ni][2], acc[mi][ni][2], fmaf(acc[mi][ni][3], acc[mi][ni][3], p1));
            }
            atomicAdd(&rowssq[wm + mi * 16 + gid], p0);
            atomicAdd(&rowssq[wm + mi * 16 + gid + 8], p1);
        }
        __syncthreads();
#pragma unroll
        for (int mi = 0; mi < 4; mi++) {
            rs[mi][0] = 1.f / fmaxf(sqrtf(rowssq[wm + mi * 16 + gid]), 1e-12f);
            rs[mi][1] = 1.f / fmaxf(sqrtf(rowssq[wm + mi * 16 + gid + 8]), 1e-12f);
        }
    }

#pragma unroll
    for (int mi = 0; mi < 4; mi++) {
        size_t row = m0 + wm + mi * 16 + gid;
#pragma unroll
        for (int ni = 0; ni < 4; ni++) {
            int col = n0 + wn + ni * 8 + tig * 2;
            float v00 = acc[mi][ni][0], v01 = acc[mi][ni][1];
            float v10 = acc[mi][ni][2], v11 = acc[mi][ni][3];
            if (NORM) {
                v00 *= rs[mi][0]; v01 *= rs[mi][0];
                v10 *= rs[mi][1]; v11 *= rs[mi][1];
            }
            if (OUTHALF) {
                __half* Ch = (__half*)Cout;
                *(__half2*)(Ch + row * CN + col) = __floats2half2_rn(v00, v01);
                *(__half2*)(Ch + (row + 8) * CN + col) = __floats2half2_rn(v10, v11);
            } else {
                float* Cf = (float*)Cout;
                *(float2*)(Cf + row * CN + col) = make_float2(v00, v01);
                *(float2*)(Cf + (row + 8) * CN + col) = make_float2(v10, v11);
            }
        }
    }
}

extern "C" void kernel_launch(void* const* d_in, const int* in_sizes, int n_in,
                              void* d_out, int out_size) {
    const float* x      = (const float*)d_in[0];
    const float* W_enc  = (const float*)d_in[1];
    const float* b_enc  = (const float*)d_in[2];
    const float* W_gc1  = (const float*)d_in[3];
    const float* b_gc1  = (const float*)d_in[4];
    const float* W_gc2  = (const float*)d_in[5];
    const float* b_gc2  = (const float*)d_in[6];
    const float* gamma1 = (const float*)d_in[7];
    const float* beta1  = (const float*)d_in[8];
    const float* gamma2 = (const float*)d_in[9];
    const float* beta2  = (const float*)d_in[10];
    const float* W_p1   = (const float*)d_in[11];
    const float* b_p1   = (const float*)d_in[12];
    const float* W_p2   = (const float*)d_in[13];
    const float* b_p2   = (const float*)d_in[14];
    float* out = (float*)d_out;

    // Resolve device addresses of __device__ globals (host shadow != device ptr).
    __half *bufA = 0, *bufB = 0, *z = 0, *wp1t = 0, *wp2t = 0, *wgt1 = 0, *wgt2 = 0;
    cudaGetSymbolAddress((void**)&bufA, g_bufA);
    cudaGetSymbolAddress((void**)&bufB, g_bufB);
    cudaGetSymbolAddress((void**)&z,    g_z);
    cudaGetSymbolAddress((void**)&wp1t, g_wp1t);
    cudaGetSymbolAddress((void**)&wp2t, g_wp2t);
    cudaGetSymbolAddress((void**)&wgt1, g_wgt1);
    cudaGetSymbolAddress((void**)&wgt2, g_wgt2);

    cudaFuncSetAttribute((const void*)k_pmma<1088, 256, 1, 1, 0, 1>,
                         cudaFuncAttributeMaxDynamicSharedMemorySize, PH_SMEM);
    cudaFuncSetAttribute((const void*)k_pmma<256, 128, 0, 0, 1, 0>,
                         cudaFuncAttributeMaxDynamicSharedMemorySize, PH_SMEM);
    cudaFuncSetAttribute((const void*)k_gc<1>,
                         cudaFuncAttributeMaxDynamicSharedMemorySize, GC1_SMEM);
    cudaFuncSetAttribute((const void*)k_gc<2>,
                         cudaFuncAttributeMaxDynamicSharedMemorySize, GC2_SMEM);

    int B = in_sizes[0] / 34;        // x is (B,17,2)
    if (B <= 0) return;
    size_t B64 = (size_t)B * 64;
    double invN = 1.0 / ((double)B * 64.0);

    // merged prep: stats zero + 4 weight transposes
    k_prep<<<1249, 256>>>(W_p1, W_p2, W_gc1, W_gc2, wp1t, wp2t, wgt1, wgt2);
    // BN1 stats directly from x
    k_st<1><<<STATS_GRID, 256>>>(x, W_enc, b_enc, B, 0, 0);
    k_fin<<<1, 32>>>(gamma1, beta1, invN, 0);
    // gc1 fused enc+agg+BN1+GEMM (x staged in smem) -> h2 planes (fp16) in bufB
    k_gc<1><<<dim3(17, B / 128), 256, GC1_SMEM>>>(x, W_enc, b_enc, wgt1, b_gc1, bufB, B64);
    // BN2 stats from h2 planes
    k_st<0><<<STATS_GRID, 256>>>(bufB, 0, 0, B, B64, 1);
    k_fin<<<1, 32>>>(gamma2, beta2, invN, 1);
    // gc2 fused agg+BN2+GEMM -> pooled planes (fp16) in bufA
    k_gc<2><<<dim3(17, B / 128), 256, GC2_SMEM>>>(bufB, 0, 0, wgt2, b_gc2, bufA, B64);
    // p1 (fp16 mma, node-major A gather): z = relu(pooled @ W_p1 + b_p1) -> z (B,256)
    k_pmma<1088, 256, 1, 1, 0, 1><<<dim3(2, B / 128), 256, PH_SMEM>>>(bufA, wp1t, b_p1, z, B64);
    // p2 (fp16 mma) + fused L2 normalize -> out (B,128) fp32
    k_pmma<256, 128, 0, 0, 1, 0><<<dim3(1, B / 128), 256, PH_SMEM>>>(z, wp2t, b_p2, out, 0);
}